// round 8
// baseline (speedup 1.0000x reference)
#include <cuda_runtime.h>
#include <cuda_fp16.h>
#include <cstdint>

#define NB 32
#define ND 64
#define NT 4096
#define NK 1024
#define NTOK (NB*NT)          // 131072 tokens
#define OUTQ (NB*ND*NT)       // 8388608 quantized elements

#define CBSTRIDE 72           // ushorts per code row: [H(64) | pad(8)] = 144B
#define CHUNK_CODES 128
#define NCHUNK (NK/CHUNK_CODES)                // 8
#define CHUNK_BYTES (CHUNK_CODES*CBSTRIDE*2)   // 18432
#define CHUNK_16B (CHUNK_BYTES/16)             // 1152

#define SX_STRIDE 68          // floats per dim row (conflict-free)
#define SMEM_SX_BYTES (64*SX_STRIDE*4)         // 17408
#define SMEM_CB0 SMEM_SX_BYTES
#define SMEM_CB1 (SMEM_CB0 + CHUNK_BYTES)
#define SMEM_TOTAL (SMEM_CB1 + CHUNK_BYTES)    // 54272

#define TAUC 1.05e-3f         // TAU = TAUC * ||x||  (hard err bound 9.77e-4*||x||)
#define GT_TPB 256
#define NPART 2048            // gather blocks (64 tokens each)

// Scratch (no allocations allowed)
__device__ int            g_idx[NTOK];
__device__ float          g_part[NPART];
__device__ unsigned short g_cb[NK * CBSTRIDE];   // codebook fp16 H, padded rows

// ============================ helpers ============================
static __device__ __forceinline__ uint32_t smem_to_u32(const void* p) {
    uint32_t a;
    asm("{ .reg .u64 tmp; cvta.to.shared.u64 tmp, %1; cvt.u32.u64 %0, tmp; }" : "=r"(a) : "l"(p));
    return a;
}
static __device__ __forceinline__ void cp_async16(uint32_t dst, const void* src) {
    asm volatile("cp.async.cg.shared.global [%0], [%1], 16;" :: "r"(dst), "l"(src) : "memory");
}
static __device__ __forceinline__ void cp_commit() {
    asm volatile("cp.async.commit_group;" ::: "memory");
}
static __device__ __forceinline__ void cp_wait1() {
    asm volatile("cp.async.wait_group 1;" ::: "memory");
}
static __device__ __forceinline__ void cp_wait0() {
    asm volatile("cp.async.wait_group 0;" ::: "memory");
}
static __device__ __forceinline__ void ldmatrix_x4(uint32_t& r0, uint32_t& r1,
                                                   uint32_t& r2, uint32_t& r3, uint32_t a) {
    asm volatile("ldmatrix.sync.aligned.m8n8.x4.shared.b16 {%0,%1,%2,%3}, [%4];"
        : "=r"(r0), "=r"(r1), "=r"(r2), "=r"(r3) : "r"(a));
}
static __device__ __forceinline__ void mma_f16(float* c,
                                               uint32_t a0, uint32_t a1, uint32_t a2, uint32_t a3,
                                               uint32_t b0, uint32_t b1) {
    asm volatile("mma.sync.aligned.m16n8k16.row.col.f32.f16.f16.f32 "
        "{%0,%1,%2,%3}, {%4,%5,%6,%7}, {%8,%9}, {%0,%1,%2,%3};"
        : "+f"(c[0]), "+f"(c[1]), "+f"(c[2]), "+f"(c[3])
        : "r"(a0), "r"(a1), "r"(a2), "r"(a3), "r"(b0), "r"(b1));
}
static __device__ __forceinline__ uint32_t packh(__half a, __half b) {
    return (uint32_t)__half_as_ushort(a) | ((uint32_t)__half_as_ushort(b) << 16);
}
// running top-2 update (ascending idx scan; first-max semantics)
static __device__ __forceinline__ void upd(float v, int idx, float& b, int& bi,
                                           float& s, int& si) {
    if (v > s) {
        if (v > b) { s = b; si = bi; b = v; bi = idx; }
        else       { s = v; si = idx; }
    }
}
// merge another top-2 into mine ((value desc, idx asc) priority)
static __device__ __forceinline__ void mrg(float& b, int& bi, float& s, int& si,
                                           float ob, int obi, float os, int osi) {
    if (ob > b || (ob == b && obi < bi)) {
        if (b > os || (b == os && bi < osi)) { s = b;  si = bi; }
        else                                 { s = os; si = osi; }
        b = ob; bi = obi;
    } else if (ob > s || (ob == s && obi < si)) {
        s = ob; si = obi;
    }
}

// ---------------------------------------------------------------------------
// Kernel 0: codebook -> fp16 H, padded 144B rows.
// ---------------------------------------------------------------------------
__global__ void vq_prep_kernel(const float* __restrict__ emb)
{
    int i = blockIdx.x * blockDim.x + threadIdx.x;
    if (i >= NK * ND) return;
    int code = i >> 6, d = i & 63;
    g_cb[code * CBSTRIDE + d] = __half_as_ushort(__float2half_rn(emb[i]));
}

// ---------------------------------------------------------------------------
// Kernel 1: fp16 mma argmax. CTA = 64 tokens (8 warps x 8 tokens).
// x = h + m (fp16 split, exact to 2^-22); e ~= H (fp16, err <= 2^-11||e||).
// score = h.H + m.H; dropped |x.(e-H)| <= 2^-11 ||x||  (hard bound).
// Per-token TAU = 1.05e-3*||x||; margin < TAU -> exact fp32 full rescan.
// 8 MMA + 4 LDSM per 16-code tile (vs 12+8 in the bf16 3-product version).
// ---------------------------------------------------------------------------
__global__ void __launch_bounds__(256, 2) vq_mma_argmax_kernel(
        const float* __restrict__ in, const float* __restrict__ emb,
        float* __restrict__ out)
{
    extern __shared__ float sx[];          // [64 dims][SX_STRIDE] fp32, then code bufs
    const uint32_t sbase = smem_to_u32(sx);
    const int tid  = threadIdx.x;
    const int lane = tid & 31;
    const int w    = tid >> 5;
    const int gid  = lane >> 2;
    const int tig  = lane & 3;

    const int n0 = blockIdx.x * 64;
    const int b  = n0 >> 12;
    const int t0 = n0 & (NT - 1);

    // stage x tile [64 d][64 t] fp32, coalesced
    {
        const float4* src = reinterpret_cast<const float4*>(in + (size_t)b * ND * NT + t0);
#pragma unroll
        for (int k = 0; k < 4; k++) {
            int i = tid + k * 256;
            int d = i >> 4, q = i & 15;
            float4 v = src[(size_t)d * (NT / 4) + q];
            *reinterpret_cast<float4*>(sx + d * SX_STRIDE + q * 4) = v;
        }
    }
    // preload code chunk 0
    for (int i = tid; i < CHUNK_16B; i += 256)
        cp_async16(sbase + SMEM_CB0 + i * 16, (const char*)g_cb + i * 16);
    cp_commit();
    __syncthreads();   // sx visible

    // build token-side fragments (B operand): token = w*8 + gid; also ||x||^2
    const int tok = w * 8 + gid;
    uint32_t bh[8], bm[8];
    float sq = 0.f;
#pragma unroll
    for (int j = 0; j < 4; j++) {
        int d0 = j * 16 + 2 * tig;
        float v0 = sx[d0 * SX_STRIDE + tok];
        float v1 = sx[(d0 + 1) * SX_STRIDE + tok];
        float v2 = sx[(d0 + 8) * SX_STRIDE + tok];
        float v3 = sx[(d0 + 9) * SX_STRIDE + tok];
        sq += v0 * v0 + v1 * v1 + v2 * v2 + v3 * v3;
        __half h0 = __float2half_rn(v0), h1 = __float2half_rn(v1);
        __half h2 = __float2half_rn(v2), h3 = __float2half_rn(v3);
        bh[2*j]   = packh(h0, h1);
        bh[2*j+1] = packh(h2, h3);
        bm[2*j]   = packh(__float2half_rn(v0 - __half2float(h0)),
                          __float2half_rn(v1 - __half2float(h1)));
        bm[2*j+1] = packh(__float2half_rn(v2 - __half2float(h2)),
                          __float2half_rn(v3 - __half2float(h3)));
    }
    // full ||x||^2 of token 'gid' (reduce over the 4 tig lanes)
    sq += __shfl_xor_sync(0xffffffffu, sq, 1);
    sq += __shfl_xor_sync(0xffffffffu, sq, 2);

    float bestv[2] = { -3.0e38f, -3.0e38f }, secv[2] = { -3.0e38f, -3.0e38f };
    int   besti[2] = { 0, 0 },               seci[2] = { 0, 0 };

    const uint32_t lmoff = (uint32_t)((lane & 15) * (CBSTRIDE * 2) + ((lane >> 4) * 16));

    for (int c = 0; c < NCHUNK; c++) {
        const uint32_t bufo = (c & 1) ? SMEM_CB1 : SMEM_CB0;
        if (c + 1 < NCHUNK) {
            const uint32_t nbufo = (c & 1) ? SMEM_CB0 : SMEM_CB1;
            const char* src = (const char*)g_cb + (size_t)(c + 1) * CHUNK_BYTES;
            for (int i = tid; i < CHUNK_16B; i += 256)
                cp_async16(sbase + nbufo + i * 16, src + i * 16);
            cp_commit();
            cp_wait1();
        } else {
            cp_wait0();
        }
        __syncthreads();

#pragma unroll 2
        for (int mt = 0; mt < 8; mt++) {
            uint32_t lm = sbase + bufo + lmoff + (uint32_t)(mt * 16 * CBSTRIDE * 2);
            uint32_t AH[16];
#pragma unroll
            for (int jj = 0; jj < 4; jj++)
                ldmatrix_x4(AH[4*jj], AH[4*jj+1], AH[4*jj+2], AH[4*jj+3], lm + jj * 32);
            // 2 independent chains: h.H and m.H
            float p[4] = {0,0,0,0}, q[4] = {0,0,0,0};
#pragma unroll
            for (int jj = 0; jj < 4; jj++) {
                mma_f16(p, AH[4*jj], AH[4*jj+1], AH[4*jj+2], AH[4*jj+3], bh[2*jj], bh[2*jj+1]);
                mma_f16(q, AH[4*jj], AH[4*jj+1], AH[4*jj+2], AH[4*jj+3], bm[2*jj], bm[2*jj+1]);
            }
            const int ib = c * CHUNK_CODES + mt * 16;
            float f0 = p[0] + q[0];
            float f1 = p[1] + q[1];
            float f2 = p[2] + q[2];
            float f3 = p[3] + q[3];
            upd(f0, ib + gid,     bestv[0], besti[0], secv[0], seci[0]);
            upd(f1, ib + gid,     bestv[1], besti[1], secv[1], seci[1]);
            upd(f2, ib + gid + 8, bestv[0], besti[0], secv[0], seci[0]);
            upd(f3, ib + gid + 8, bestv[1], besti[1], secv[1], seci[1]);
        }
        __syncthreads();
    }

    // butterfly merge of top-2 across the 8 row-groups (lanes differing in bits 2..4)
#pragma unroll
    for (int off = 4; off <= 16; off <<= 1) {
#pragma unroll
        for (int col = 0; col < 2; col++) {
            float ob  = __shfl_xor_sync(0xffffffffu, bestv[col], off);
            int   obi = __shfl_xor_sync(0xffffffffu, besti[col], off);
            float os  = __shfl_xor_sync(0xffffffffu, secv[col],  off);
            int   osi = __shfl_xor_sync(0xffffffffu, seci[col],  off);
            mrg(bestv[col], besti[col], secv[col], seci[col], ob, obi, os, osi);
        }
    }

    // per-token TAU: lanes 0..3 decide for tokens 2*lane (col0), 2*lane+1 (col1).
    // sq for token g lives in lanes 4g..4g+3 -> fetch via shfl.
    float sq0 = __shfl_sync(0xffffffffu, sq, (lane * 8) & 31);
    float sq1 = __shfl_sync(0xffffffffu, sq, (lane * 8 + 4) & 31);
    float tau0 = TAUC * sqrtf(sq0);
    float tau1 = TAUC * sqrtf(sq1);

    // near-tie rescue: full exact fp32 rescan, warp-cooperative (uniform control)
    unsigned m0 = __ballot_sync(0xffffffffu, (lane < 4) && (bestv[0] - secv[0] < tau0)) & 0xFu;
    unsigned m1 = __ballot_sync(0xffffffffu, (lane < 4) && (bestv[1] - secv[1] < tau1)) & 0xFu;
    if (m0 | m1) {
        for (int l = 0; l < 4; l++) {
#pragma unroll
            for (int col = 0; col < 2; col++) {
                unsigned mm = col ? m1 : m0;
                if ((mm >> l) & 1u) {
                    const int ts = w * 8 + 2 * l + col;   // token slot in block-tile
                    float bb = -3.0e38f; int bi = 0;
                    for (int cc = lane; cc < NK; cc += 32) {
                        const float* e = emb + (size_t)cc * ND;
                        float a0 = 0.f, a1 = 0.f, a2 = 0.f, a3 = 0.f;
#pragma unroll
                        for (int d = 0; d < ND; d += 4) {
                            a0 = fmaf(sx[d * SX_STRIDE + ts],       e[d],     a0);
                            a1 = fmaf(sx[(d + 1) * SX_STRIDE + ts], e[d + 1], a1);
                            a2 = fmaf(sx[(d + 2) * SX_STRIDE + ts], e[d + 2], a2);
                            a3 = fmaf(sx[(d + 3) * SX_STRIDE + ts], e[d + 3], a3);
                        }
                        float v = (a0 + a1) + (a2 + a3);
                        if (v > bb) { bb = v; bi = cc; }
                    }
#pragma unroll
                    for (int off = 16; off; off >>= 1) {
                        float ov = __shfl_xor_sync(0xffffffffu, bb, off);
                        int   oi = __shfl_xor_sync(0xffffffffu, bi, off);
                        if (ov > bb || (ov == bb && oi < bi)) { bb = ov; bi = oi; }
                    }
                    if (lane == l) besti[col] = bi;
                }
            }
        }
    }

    if (lane < 4) {
        const int n = n0 + w * 8 + 2 * lane;
        g_idx[n]     = besti[0];
        g_idx[n + 1] = besti[1];
        out[OUTQ + 2 + n]     = (float)besti[0];
        out[OUTQ + 2 + n + 1] = (float)besti[1];
    }
}

// ---------------------------------------------------------------------------
// Kernel 2: gather quantized output + loss partials (coalesced, smem-staged).
// commitment_loss == codebook_loss forward == mean((flat - emb_unnorm[idx])^2)
// ---------------------------------------------------------------------------
__global__ void __launch_bounds__(GT_TPB) vq_gather_loss_kernel(
        const float* __restrict__ in, const float* __restrict__ emb,
        const float* __restrict__ embu, float* __restrict__ out)
{
    __shared__ int   sidx[64];
    __shared__ float sq[64 * 65];
    __shared__ float su[64 * 65];

    const int tid = threadIdx.x;
    const int n0  = blockIdx.x * 64;
    const int b   = n0 >> 12;
    const int t0  = n0 & (NT - 1);

    if (tid < 64) sidx[tid] = g_idx[n0 + tid];
    __syncthreads();

    {
        const int tok = tid >> 2;
        const int q   = tid & 3;
        const int code = sidx[tok];
        const float4* e4 = reinterpret_cast<const float4*>(emb  + (size_t)code * ND);
        const float4* u4 = reinterpret_cast<const float4*>(embu + (size_t)code * ND);
#pragma unroll
        for (int j = 0; j < 4; j++) {
            float4 f = e4[q * 4 + j];
            float4 u = u4[q * 4 + j];
            int base = tok * 65 + q * 16 + j * 4;
            sq[base] = f.x; sq[base+1] = f.y; sq[base+2] = f.z; sq[base+3] = f.w;
            su[base] = u.x; su[base+1] = u.y; su[base+2] = u.z; su[base+3] = u.w;
        }
    }
    __syncthreads();

    const int d  = tid >> 2;
    const int j0 = (tid & 3) * 16;
    const size_t gbase = (size_t)b * ND * NT + (size_t)d * NT + t0 + j0;
    float lsum = 0.f;
#pragma unroll
    for (int i = 0; i < 16; i++) {
        float xi = in[gbase + i];
        out[gbase + i] = sq[(j0 + i) * 65 + d];
        float df = xi - su[(j0 + i) * 65 + d];
        lsum += df * df;
    }

#pragma unroll
    for (int o = 16; o; o >>= 1) lsum += __shfl_xor_sync(0xffffffffu, lsum, o);
    __shared__ float ws[GT_TPB / 32];
    if ((tid & 31) == 0) ws[tid >> 5] = lsum;
    __syncthreads();
    if (tid < 32) {
        float v = (tid < GT_TPB / 32) ? ws[tid] : 0.f;
#pragma unroll
        for (int o = 4; o; o >>= 1) v += __shfl_xor_sync(0xffffffffu, v, o);
        if (tid == 0) g_part[blockIdx.x] = v;
    }
}

// ---------------------------------------------------------------------------
// Kernel 3: final loss reduction (double precision), write scalars.
// ---------------------------------------------------------------------------
__global__ void vq_finalize_kernel(float* __restrict__ out)
{
    __shared__ double sd[256];
    double s = 0.0;
    for (int i = threadIdx.x; i < NPART; i += 256) s += (double)g_part[i];
    sd[threadIdx.x] = s;
    __syncthreads();
    for (int o = 128; o; o >>= 1) {
        if (threadIdx.x < o) sd[threadIdx.x] += sd[threadIdx.x + o];
        __syncthreads();
    }
    if (threadIdx.x == 0) {
        float m = (float)(sd[0] / (double)OUTQ);
        out[OUTQ]     = m;   // commitment_loss
        out[OUTQ + 1] = m;   // codebook_loss (numerically identical forward)
    }
}

extern "C" void kernel_launch(void* const* d_in, const int* in_sizes, int n_in,
                              void* d_out, int out_size) {
    const float* in   = (const float*)d_in[0];   // [32, 64, 4096] fp32
    const float* emb  = (const float*)d_in[1];   // [1024, 64] fp32 (pre-normalized)
    const float* embu = (const float*)d_in[2];   // [1024, 64] fp32
    float* out = (float*)d_out;

    static int configured = 0;
    if (!configured) {
        cudaFuncSetAttribute(vq_mma_argmax_kernel,
                             cudaFuncAttributeMaxDynamicSharedMemorySize, SMEM_TOTAL);
        configured = 1;
    }

    vq_prep_kernel<<<(NK * ND) / 256, 256>>>(emb);
    vq_mma_argmax_kernel<<<NTOK / 64, 256, SMEM_TOTAL>>>(in, emb, out);
    vq_gather_loss_kernel<<<NPART, GT_TPB>>>(in, emb, embu, out);
    vq_finalize_kernel<<<1, 256>>>(out);
}

// round 10
// speedup vs baseline: 1.8761x; 1.8761x over previous
#include <cuda_runtime.h>
#include <cuda_bf16.h>
#include <cstdint>

#define NB 32
#define ND 64
#define NT 4096
#define NK 1024
#define NTOK (NB*NT)          // 131072 tokens
#define OUTQ (NB*ND*NT)       // 8388608 quantized elements

#define NTILE (NTOK/64)       // 2048 64-token tiles
#define AGRID (NTILE*2)       // 4096 CTAs: half tensor, half fma
#define TCHUNKS 4             // tensor: codes 0..511
#define FCHUNKS 4             // fma:    codes 512..1023
#define FBASE 512

#define CBSTRIDE 136          // ushorts per code row: [H(64)|M(64)|pad(8)] = 272B
#define TCHUNK_BYTES (128*CBSTRIDE*2)   // 34816
#define TCHUNK_16B (TCHUNK_BYTES/16)    // 2176
#define FCHUNK_BYTES (128*ND*4)         // 32768
#define FCHUNK_16B (FCHUNK_BYTES/16)    // 2048

#define SX_STRIDE 68          // floats per dim row (conflict-free)
#define SMEM_SX_BYTES (64*SX_STRIDE*4)         // 17408
// tensor view
#define SMEM_TCB0 17408
#define SMEM_TCB1 52224
// fma view (same CTA never uses both views)
#define SMEM_FCB0 17408
#define SMEM_FCB1 50176
#define SMEM_FMRG 82944       // 4096 B: fbv[256], fsv[256], fbi[256], fsi[256]
#define SMEM_SZ   87040

#define TAU 1e-3f
#define GT_TPB 256
#define NPART 2048

// Scratch (no allocations allowed)
__device__ float g_part[NPART];
__device__ unsigned short g_cb[FBASE * CBSTRIDE];   // bf16 [H|M] rows, codes 0..511
// per-token top-2 partials from each path
__device__ float g_tbv[NTOK], g_tsv[NTOK], g_fbv[NTOK], g_fsv[NTOK];
__device__ int   g_tbi[NTOK], g_tsi[NTOK], g_fbi[NTOK], g_fsi[NTOK];

// ============================ helpers ============================
static __device__ __forceinline__ uint32_t smem_to_u32(const void* p) {
    uint32_t a;
    asm("{ .reg .u64 tmp; cvta.to.shared.u64 tmp, %1; cvt.u32.u64 %0, tmp; }" : "=r"(a) : "l"(p));
    return a;
}
static __device__ __forceinline__ void cp_async16(uint32_t dst, const void* src) {
    asm volatile("cp.async.cg.shared.global [%0], [%1], 16;" :: "r"(dst), "l"(src) : "memory");
}
static __device__ __forceinline__ void cp_commit() {
    asm volatile("cp.async.commit_group;" ::: "memory");
}
static __device__ __forceinline__ void cp_wait1() {
    asm volatile("cp.async.wait_group 1;" ::: "memory");
}
static __device__ __forceinline__ void cp_wait0() {
    asm volatile("cp.async.wait_group 0;" ::: "memory");
}
static __device__ __forceinline__ void ldmatrix_x4(uint32_t& r0, uint32_t& r1,
                                                   uint32_t& r2, uint32_t& r3, uint32_t a) {
    asm volatile("ldmatrix.sync.aligned.m8n8.x4.shared.b16 {%0,%1,%2,%3}, [%4];"
        : "=r"(r0), "=r"(r1), "=r"(r2), "=r"(r3) : "r"(a));
}
static __device__ __forceinline__ void mma_bf16(float* c,
                                                uint32_t a0, uint32_t a1, uint32_t a2, uint32_t a3,
                                                uint32_t b0, uint32_t b1) {
    asm volatile("mma.sync.aligned.m16n8k16.row.col.f32.bf16.bf16.f32 "
        "{%0,%1,%2,%3}, {%4,%5,%6,%7}, {%8,%9}, {%0,%1,%2,%3};"
        : "+f"(c[0]), "+f"(c[1]), "+f"(c[2]), "+f"(c[3])
        : "r"(a0), "r"(a1), "r"(a2), "r"(a3), "r"(b0), "r"(b1));
}
static __device__ __forceinline__ uint32_t packbf(__nv_bfloat16 a, __nv_bfloat16 b) {
    return (uint32_t)__bfloat16_as_ushort(a) | ((uint32_t)__bfloat16_as_ushort(b) << 16);
}
static __device__ __forceinline__ unsigned long long pack2(float lo, float hi) {
    unsigned long long r;
    asm("mov.b64 %0, {%1, %2};" : "=l"(r) : "f"(lo), "f"(hi));
    return r;
}
static __device__ __forceinline__ float2 unpack2(unsigned long long v) {
    float2 f;
    asm("mov.b64 {%0, %1}, %2;" : "=f"(f.x), "=f"(f.y) : "l"(v));
    return f;
}
static __device__ __forceinline__ void ffma2(unsigned long long &acc,
                                             unsigned long long a, unsigned long long b) {
    asm("fma.rn.f32x2 %0, %1, %2, %3;" : "=l"(acc) : "l"(a), "l"(b), "l"(acc));
}
static __device__ __forceinline__ unsigned long long fadd2(unsigned long long a,
                                                           unsigned long long b) {
    unsigned long long r;
    asm("add.rn.f32x2 %0, %1, %2;" : "=l"(r) : "l"(a), "l"(b));
    return r;
}
// running top-2 update (ascending idx scan; first-max semantics)
static __device__ __forceinline__ void upd(float v, int idx, float& b, int& bi,
                                           float& s, int& si) {
    if (v > s) {
        if (v > b) { s = b; si = bi; b = v; bi = idx; }
        else       { s = v; si = idx; }
    }
}
// merge another top-2 into mine ((value desc, idx asc) priority)
static __device__ __forceinline__ void mrg2(float& b, int& bi, float& s, int& si,
                                            float ob, int obi, float os, int osi) {
    if (ob > b || (ob == b && obi < bi)) {
        if (b > os || (b == os && bi < osi)) { s = b;  si = bi; }
        else                                 { s = os; si = osi; }
        b = ob; bi = obi;
    } else if (ob > s || (ob == s && obi < si)) {
        s = ob; si = obi;
    }
}

// ---------------------------------------------------------------------------
// Kernel 0: split codebook rows (codes 0..511) into [H | M] bf16.
// ---------------------------------------------------------------------------
__global__ void vq_prep_kernel(const float* __restrict__ emb)
{
    int i = blockIdx.x * blockDim.x + threadIdx.x;
    if (i >= FBASE * ND) return;
    int code = i >> 6, d = i & 63;
    float v = emb[i];
    __nv_bfloat16 h = __float2bfloat16_rn(v);
    __nv_bfloat16 m = __float2bfloat16_rn(v - __bfloat162float(h));
    g_cb[code * CBSTRIDE + d]      = __bfloat16_as_ushort(h);
    g_cb[code * CBSTRIDE + 64 + d] = __bfloat16_as_ushort(m);
}

// ---------------------------------------------------------------------------
// Kernel 1: hybrid argmax, CTA-type split. 4096 CTAs of 256 threads.
//  (bid&7)<4  -> TENSOR CTA: R4 bf16 3-product HMMA path, codes 0..511
//  (bid&7)>=4 -> FMA CTA:    R1 f32x2 exact path,        codes 512..1023
// Co-resident CTA pair on an SM differs by bid+148; 148%8==4 -> opposite
// types -> tensor pipe and fma pipe both busy on every SM.
// Each writes per-token top-2 partials; merge+rescue happen in the gather.
// ---------------------------------------------------------------------------
__global__ void __launch_bounds__(256, 2) vq_hybrid_argmax_kernel(
        const float* __restrict__ in, const float* __restrict__ emb,
        float* __restrict__ out)
{
    extern __shared__ float sx[];
    const uint32_t sbase = smem_to_u32(sx);
    const int tid  = threadIdx.x;
    const int lane = tid & 31;
    const int w    = tid >> 5;

    const int bid   = blockIdx.x;
    const int tile  = (bid >> 3) * 4 + (bid & 3);
    const bool is_fma = (bid & 7) >= 4;
    const int n0 = tile * 64;
    const int b  = n0 >> 12;
    const int t0 = n0 & (NT - 1);

    // stage x tile [64 d][64 t] fp32, coalesced (both types)
    {
        const float4* src = reinterpret_cast<const float4*>(in + (size_t)b * ND * NT + t0);
#pragma unroll
        for (int k = 0; k < 4; k++) {
            int i = tid + k * 256;
            int d = i >> 4, q = i & 15;
            float4 v = src[(size_t)d * (NT / 4) + q];
            *reinterpret_cast<float4*>(sx + d * SX_STRIDE + q * 4) = v;
        }
    }

    if (!is_fma) {
        // ===================== TENSOR CTA: codes 0..511 =====================
        for (int i = tid; i < TCHUNK_16B; i += 256)
            cp_async16(sbase + SMEM_TCB0 + i * 16, (const char*)g_cb + i * 16);
        cp_commit();
        __syncthreads();

        const int gid = lane >> 2;
        const int tig = lane & 3;
        const int tok = w * 8 + gid;
        uint32_t bh[8], bm[8];
#pragma unroll
        for (int j = 0; j < 4; j++) {
            int d0 = j * 16 + 2 * tig;
            float v0 = sx[d0 * SX_STRIDE + tok];
            float v1 = sx[(d0 + 1) * SX_STRIDE + tok];
            float v2 = sx[(d0 + 8) * SX_STRIDE + tok];
            float v3 = sx[(d0 + 9) * SX_STRIDE + tok];
            __nv_bfloat16 h0 = __float2bfloat16_rn(v0), h1 = __float2bfloat16_rn(v1);
            __nv_bfloat16 h2 = __float2bfloat16_rn(v2), h3 = __float2bfloat16_rn(v3);
            bh[2*j]   = packbf(h0, h1);
            bh[2*j+1] = packbf(h2, h3);
            bm[2*j]   = packbf(__float2bfloat16_rn(v0 - __bfloat162float(h0)),
                               __float2bfloat16_rn(v1 - __bfloat162float(h1)));
            bm[2*j+1] = packbf(__float2bfloat16_rn(v2 - __bfloat162float(h2)),
                               __float2bfloat16_rn(v3 - __bfloat162float(h3)));
        }

        float bestv[2] = { -3.0e38f, -3.0e38f }, secv[2] = { -3.0e38f, -3.0e38f };
        int   besti[2] = { 0, 0 },               seci[2] = { 0, 0 };
        const uint32_t lmoff = (uint32_t)((lane & 15) * (CBSTRIDE * 2) + ((lane >> 4) * 16));

        for (int c = 0; c < TCHUNKS; c++) {
            const uint32_t bufo = (c & 1) ? SMEM_TCB1 : SMEM_TCB0;
            if (c + 1 < TCHUNKS) {
                const uint32_t nb = (c & 1) ? SMEM_TCB0 : SMEM_TCB1;
                const char* src = (const char*)g_cb + (size_t)(c + 1) * TCHUNK_BYTES;
                for (int i = tid; i < TCHUNK_16B; i += 256)
                    cp_async16(sbase + nb + i * 16, src + i * 16);
                cp_commit();
                cp_wait1();
            } else {
                cp_wait0();
            }
            __syncthreads();

#pragma unroll 2
            for (int mt = 0; mt < 8; mt++) {
                uint32_t lm = sbase + bufo + lmoff + (uint32_t)(mt * 16 * CBSTRIDE * 2);
                uint32_t AH[16], AM[16];
#pragma unroll
                for (int jj = 0; jj < 4; jj++) {
                    ldmatrix_x4(AH[4*jj], AH[4*jj+1], AH[4*jj+2], AH[4*jj+3], lm + jj * 32);
                    ldmatrix_x4(AM[4*jj], AM[4*jj+1], AM[4*jj+2], AM[4*jj+3], lm + 128 + jj * 32);
                }
                float p[4] = {0,0,0,0}, q[4] = {0,0,0,0}, r[4] = {0,0,0,0};
#pragma unroll
                for (int jj = 0; jj < 4; jj++) {
                    mma_bf16(p, AH[4*jj], AH[4*jj+1], AH[4*jj+2], AH[4*jj+3], bh[2*jj], bh[2*jj+1]);
                    mma_bf16(q, AM[4*jj], AM[4*jj+1], AM[4*jj+2], AM[4*jj+3], bh[2*jj], bh[2*jj+1]);
                    mma_bf16(r, AH[4*jj], AH[4*jj+1], AH[4*jj+2], AH[4*jj+3], bm[2*jj], bm[2*jj+1]);
                }
                const int ib = c * 128 + mt * 16;
                float f0 = p[0] + q[0] + r[0];
                float f1 = p[1] + q[1] + r[1];
                float f2 = p[2] + q[2] + r[2];
                float f3 = p[3] + q[3] + r[3];
                upd(f0, ib + gid,     bestv[0], besti[0], secv[0], seci[0]);
                upd(f1, ib + gid,     bestv[1], besti[1], secv[1], seci[1]);
                upd(f2, ib + gid + 8, bestv[0], besti[0], secv[0], seci[0]);
                upd(f3, ib + gid + 8, bestv[1], besti[1], secv[1], seci[1]);
            }
            __syncthreads();
        }

#pragma unroll
        for (int off = 4; off <= 16; off <<= 1)
#pragma unroll
            for (int col = 0; col < 2; col++) {
                float ob  = __shfl_xor_sync(0xffffffffu, bestv[col], off);
                int   obi = __shfl_xor_sync(0xffffffffu, besti[col], off);
                float os  = __shfl_xor_sync(0xffffffffu, secv[col],  off);
                int   osi = __shfl_xor_sync(0xffffffffu, seci[col],  off);
                mrg2(bestv[col], besti[col], secv[col], seci[col], ob, obi, os, osi);
            }
        if (lane < 4) {
            const int n = n0 + w * 8 + 2 * lane;
            g_tbv[n] = bestv[0];   g_tsv[n] = secv[0];
            g_tbi[n] = besti[0];   g_tsi[n] = seci[0];
            g_tbv[n+1] = bestv[1]; g_tsv[n+1] = secv[1];
            g_tbi[n+1] = besti[1]; g_tsi[n+1] = seci[1];
        }
    } else {
        // ===================== FMA CTA: codes 512..1023 =====================
        {
            const char* src = (const char*)(emb + (size_t)FBASE * ND);
            for (int i = tid; i < FCHUNK_16B; i += 256)
                cp_async16(sbase + SMEM_FCB0 + i * 16, src + i * 16);
            cp_commit();
        }
        __syncthreads();

        const int tok = tid & 63;
        const int g   = tid >> 6;      // code phase 0..3
        unsigned long long xp[32];
#pragma unroll
        for (int j = 0; j < 32; j++)
            xp[j] = pack2(sx[(2*j) * SX_STRIDE + tok], sx[(2*j+1) * SX_STRIDE + tok]);

        float best = -3.0e38f, sec = -3.0e38f;
        int   bi = 0, si = 0;

        for (int c = 0; c < FCHUNKS; c++) {
            if (c + 1 < FCHUNKS) {
                const uint32_t nb = (c & 1) ? SMEM_FCB0 : SMEM_FCB1;
                const char* src = (const char*)(emb + (size_t)(FBASE + (c + 1) * 128) * ND);
                for (int i = tid; i < FCHUNK_16B; i += 256)
                    cp_async16(sbase + nb + i * 16, src + i * 16);
                cp_commit();
                cp_wait1();
            } else {
                cp_wait0();
            }
            __syncthreads();

            const char* fbuf = reinterpret_cast<const char*>(sx) +
                               ((c & 1) ? SMEM_FCB1 : SMEM_FCB0);
            const int cb0 = FBASE + c * 128;
#pragma unroll 2
            for (int k = 0; k < 32; k++) {
                const ulonglong2* row =
                    reinterpret_cast<const ulonglong2*>(fbuf + (4 * k + g) * 256);
                unsigned long long a0 = 0ull, a1 = 0ull, a2 = 0ull, a3 = 0ull;
#pragma unroll
                for (int j = 0; j < 8; j++) {
                    ulonglong2 e0 = row[2*j];
                    ulonglong2 e1 = row[2*j + 1];
                    ffma2(a0, xp[4*j + 0], e0.x);
                    ffma2(a1, xp[4*j + 1], e0.y);
                    ffma2(a2, xp[4*j + 2], e1.x);
                    ffma2(a3, xp[4*j + 3], e1.y);
                }
                unsigned long long s2 = fadd2(fadd2(a0, a1), fadd2(a2, a3));
                float2 f = unpack2(s2);
                upd(f.x + f.y, cb0 + 4 * k + g, best, bi, sec, si);
            }
            __syncthreads();
        }

        // merge the 4 code-phases per token via smem
        float* fbv = reinterpret_cast<float*>(reinterpret_cast<char*>(sx) + SMEM_FMRG);
        float* fsv = fbv + 256;
        int*   fbi = reinterpret_cast<int*>(fsv + 256);
        int*   fsi = fbi + 256;
        fbv[g * 64 + tok] = best; fsv[g * 64 + tok] = sec;
        fbi[g * 64 + tok] = bi;   fsi[g * 64 + tok] = si;
        __syncthreads();
        if (tid < 64) {
            float bv = fbv[tid], sv = fsv[tid];
            int   bI = fbi[tid], sI = fsi[tid];
#pragma unroll
            for (int gg = 1; gg < 4; gg++)
                mrg2(bv, bI, sv, sI, fbv[gg*64 + tid], fbi[gg*64 + tid],
                     fsv[gg*64 + tid], fsi[gg*64 + tid]);
            const int n = n0 + tid;
            g_fbv[n] = bv; g_fsv[n] = sv; g_fbi[n] = bI; g_fsi[n] = sI;
        }
    }
}

// ---------------------------------------------------------------------------
// Kernel 2: merge partials + near-tie exact rescue + idx write + gather +
// loss partials. Block = 64 tokens of one batch.
// ---------------------------------------------------------------------------
__global__ void __launch_bounds__(GT_TPB) vq_gather_loss_kernel(
        const float* __restrict__ in, const float* __restrict__ emb,
        const float* __restrict__ embu, float* __restrict__ out)
{
    __shared__ int   sidx[64];
    __shared__ float sq[64 * 65];
    __shared__ float su[64 * 65];

    const int tid = threadIdx.x;
    const int lane = tid & 31;
    const int w = tid >> 5;
    const int n0  = blockIdx.x * 64;
    const int b   = n0 >> 12;
    const int t0  = n0 & (NT - 1);

    if (tid < 64) {
        const int n = n0 + tid;
        float bv = g_tbv[n], sv = g_tsv[n];
        int   bi = g_tbi[n], si = g_tsi[n];
        mrg2(bv, bi, sv, si, g_fbv[n], g_fbi[n], g_fsv[n], g_fsi[n]);
        int myidx = bi;
        // near-tie rescue: exact fp32 rescan of ALL codes (warp-cooperative)
        unsigned need = __ballot_sync(0xffffffffu, bv - sv < TAU);
        while (need) {
            int l = __ffs(need) - 1;
            need &= need - 1;
            const float* xin = in + (size_t)b * ND * NT + (t0 + w * 32 + l);
            float bb = -3.0e38f; int bbi = 0;
            for (int cc = lane; cc < NK; cc += 32) {
                const float* e = emb + (size_t)cc * ND;
                float a0 = 0.f, a1 = 0.f, a2 = 0.f, a3 = 0.f;
#pragma unroll
                for (int d = 0; d < ND; d += 4) {
                    a0 = fmaf(xin[(size_t)d * NT],       e[d],     a0);
                    a1 = fmaf(xin[(size_t)(d + 1) * NT], e[d + 1], a1);
                    a2 = fmaf(xin[(size_t)(d + 2) * NT], e[d + 2], a2);
                    a3 = fmaf(xin[(size_t)(d + 3) * NT], e[d + 3], a3);
                }
                float v = (a0 + a1) + (a2 + a3);
                if (v > bb) { bb = v; bbi = cc; }
            }
#pragma unroll
            for (int off = 16; off; off >>= 1) {
                float ov = __shfl_xor_sync(0xffffffffu, bb, off);
                int   oi = __shfl_xor_sync(0xffffffffu, bbi, off);
                if (ov > bb || (ov == bb && oi < bbi)) { bb = ov; bbi = oi; }
            }
            if (lane == l) myidx = bbi;
        }
        sidx[tid] = myidx;
        out[OUTQ + 2 + n] = (float)myidx;
    }
    __syncthreads();

    {
        const int tok = tid >> 2;
        const int q   = tid & 3;
        const int code = sidx[tok];
        const float4* e4 = reinterpret_cast<const float4*>(emb  + (size_t)code * ND);
        const float4* u4 = reinterpret_cast<const float4*>(embu + (size_t)code * ND);
#pragma unroll
        for (int j = 0; j < 4; j++) {
            float4 f = e4[q * 4 + j];
            float4 u = u4[q * 4 + j];
            int base = tok * 65 + q * 16 + j * 4;
            sq[base] = f.x; sq[base+1] = f.y; sq[base+2] = f.z; sq[base+3] = f.w;
            su[base] = u.x; su[base+1] = u.y; su[base+2] = u.z; su[base+3] = u.w;
        }
    }
    __syncthreads();

    const int d  = tid >> 2;
    const int j0 = (tid & 3) * 16;
    const size_t gbase = (size_t)b * ND * NT + (size_t)d * NT + t0 + j0;
    float lsum = 0.f;
#pragma unroll
    for (int i = 0; i < 16; i++) {
        float xi = in[gbase + i];
        out[gbase + i] = sq[(j0 + i) * 65 + d];
        float df = xi - su[(j0 + i) * 65 + d];
        lsum += df * df;
    }

#pragma unroll
    for (int o = 16; o; o >>= 1) lsum += __shfl_xor_sync(0xffffffffu, lsum, o);
    __shared__ float ws[GT_TPB / 32];
    if ((tid & 31) == 0) ws[tid >> 5] = lsum;
    __syncthreads();
    if (tid < 32) {
        float v = (tid < GT_TPB / 32) ? ws[tid] : 0.f;
#pragma unroll
        for (int o = 4; o; o >>= 1) v += __shfl_xor_sync(0xffffffffu, v, o);
        if (tid == 0) g_part[blockIdx.x] = v;
    }
}

// ---------------------------------------------------------------------------
// Kernel 3: final loss reduction (double precision), write scalars.
// ---------------------------------------------------------------------------
__global__ void vq_finalize_kernel(float* __restrict__ out)
{
    __shared__ double sd[256];
    double s = 0.0;
    for (int i = threadIdx.x; i < NPART; i += 256) s += (double)g_part[i];
    sd[threadIdx.x] = s;
    __syncthreads();
    for (int o = 128; o; o >>= 1) {
        if (threadIdx.x < o) sd[threadIdx.x] += sd[threadIdx.x + o];
        __syncthreads();
    }
    if (threadIdx.x == 0) {
        float m = (float)(sd[0] / (double)OUTQ);
        out[OUTQ]     = m;   // commitment_loss
        out[OUTQ + 1] = m;   // codebook_loss (numerically identical forward)
    }
}

extern "C" void kernel_launch(void* const* d_in, const int* in_sizes, int n_in,
                              void* d_out, int out_size) {
    const float* in   = (const float*)d_in[0];   // [32, 64, 4096] fp32
    const float* emb  = (const float*)d_in[1];   // [1024, 64] fp32 (pre-normalized)
    const float* embu = (const float*)d_in[2];   // [1024, 64] fp32
    float* out = (float*)d_out;

    static int configured = 0;
    if (!configured) {
        cudaFuncSetAttribute(vq_hybrid_argmax_kernel,
                             cudaFuncAttributeMaxDynamicSharedMemorySize, SMEM_SZ);
        configured = 1;
    }

    vq_prep_kernel<<<(FBASE * ND) / 256, 256>>>(emb);
    vq_hybrid_argmax_kernel<<<AGRID, 256, SMEM_SZ>>>(in, emb, out);
    vq_gather_loss_kernel<<<NPART, GT_TPB>>>(in, emb, embu, out);
    vq_finalize_kernel<<<1, 256>>>(out);
}